// round 3
// baseline (speedup 1.0000x reference)
#include <cuda_runtime.h>

// CausalConv1d: x (4, 2048, 8192) f32, depthwise weight (2048, 1, 16), bias (2048)
// out[n,c,l] = sum_{k=0..15} x[n,c,l-15+k] * w[c,0,k] + bias[c]   (zero-pad left)
//
// OPT=16 outputs/thread: 8 coalesced LDG.128 cover the 32-float window
// x[base-16 .. base+15]; 4 STG.128 write the 16 outputs. L1 amplification
// drops from 6x (OPT=4) to 3x, unblocking the l1tex-bound roofline.

#define DIM   2048
#define LEN   8192
#define KSZ   16
#define BLOCK 256
#define OPT   16
#define TILE  (BLOCK * OPT)          // 4096
#define TILES_PER_ROW (LEN / TILE)   // 2

__global__ __launch_bounds__(BLOCK) void causal_conv1d_kernel(
    const float* __restrict__ x,
    const float* __restrict__ w,
    const float* __restrict__ bias,
    float* __restrict__ out)
{
    const int tid  = threadIdx.x;
    const int row  = blockIdx.x >> 1;                 // / TILES_PER_ROW
    const int tile = blockIdx.x & (TILES_PER_ROW - 1);
    const int ch   = row & (DIM - 1);                 // row = n*DIM + c

    const float* __restrict__ xrow = x   + (size_t)row * LEN;
    float*       __restrict__ orow = out + (size_t)row * LEN;

    const int base = tile * TILE + OPT * tid;         // first output index (mult of 16)

    // ---- window r[i] = xrow[base - 16 + i], i in [0, 32): 8 vec4 loads ----
    // Only tile 0 / thread 0 / first vector can be out of range (base-16 = -16),
    // and vectors never straddle index 0 (all offsets are multiples of 4).
    float r[OPT + KSZ];                               // 32
    #pragma unroll
    for (int j = 0; j < 8; j++) {
        const int m = base - 16 + 4 * j;
        float4 v = make_float4(0.f, 0.f, 0.f, 0.f);
        if (m >= 0) v = *reinterpret_cast<const float4*>(xrow + m);
        r[4 * j + 0] = v.x; r[4 * j + 1] = v.y;
        r[4 * j + 2] = v.z; r[4 * j + 3] = v.w;
    }

    // ---- weights: 4 warp-uniform vec4 loads (L1 broadcast), bias scalar ----
    float wr[KSZ];
    const float4* w4 = reinterpret_cast<const float4*>(w + ch * KSZ);
    #pragma unroll
    for (int q = 0; q < 4; q++) {
        float4 v = w4[q];
        wr[4 * q + 0] = v.x; wr[4 * q + 1] = v.y;
        wr[4 * q + 2] = v.z; wr[4 * q + 3] = v.w;
    }
    const float b = bias[ch];

    // ---- compute+store in groups of 4 to bound live accumulators ----
    #pragma unroll
    for (int g = 0; g < OPT / 4; g++) {
        float acc[4];
        #pragma unroll
        for (int m = 0; m < 4; m++) {
            float a = b;
            const int o = 4 * g + m;                  // output m within thread
            #pragma unroll
            for (int k = 0; k < KSZ; k++)
                a = fmaf(wr[k], r[o + 1 + k], a);
            acc[m] = a;
        }
        float4 ov; ov.x = acc[0]; ov.y = acc[1]; ov.z = acc[2]; ov.w = acc[3];
        *reinterpret_cast<float4*>(orow + base + 4 * g) = ov;
    }
}

extern "C" void kernel_launch(void* const* d_in, const int* in_sizes, int n_in,
                              void* d_out, int out_size)
{
    const float* x    = (const float*)d_in[0];
    const float* w    = (const float*)d_in[1];
    const float* bias = (const float*)d_in[2];
    float* out        = (float*)d_out;

    const int rows = 4 * DIM;                          // 8192
    const int blocks = rows * TILES_PER_ROW;           // 16384
    causal_conv1d_kernel<<<blocks, BLOCK>>>(x, w, bias, out);
}